// round 1
// baseline (speedup 1.0000x reference)
#include <cuda_runtime.h>
#include <cuda_bf16.h>
#include <cstdint>

#define N_NODES 50000
#define N_EDGES 800000
#define DIM 128

// Scratch for H = relu(V @ W^T + b)  [N_NODES, DIM]
__device__ float g_H[N_NODES * DIM];
// 1 if indices are int32, 0 if int64. Recomputed every launch (deterministic).
__device__ int g_idx32;

// ---------------------------------------------------------------------------
// Detect index dtype: int64 indices < 50000 have all-zero high words.
// ---------------------------------------------------------------------------
__global__ void detect_idx_dtype(const unsigned int* __restrict__ srcw) {
    __shared__ int found;
    if (threadIdx.x == 0) found = 0;
    __syncthreads();
    // scan odd 32-bit words of the first 2048 8-byte slots
    for (int i = threadIdx.x; i < 2048; i += blockDim.x) {
        if (srcw[2 * i + 1] != 0u) found = 1;
    }
    __syncthreads();
    if (threadIdx.x == 0) g_idx32 = found;
}

// ---------------------------------------------------------------------------
// Zero the output (harness poisons it to 0xAA). 0.0f == int 0 works as the
// identity for non-negative-float integer atomicMax.
// ---------------------------------------------------------------------------
__global__ void zero_out_kernel(float4* __restrict__ out) {
    int i = blockIdx.x * blockDim.x + threadIdx.x;
    if (i < N_NODES * (DIM / 4)) out[i] = make_float4(0.f, 0.f, 0.f, 0.f);
}

// ---------------------------------------------------------------------------
// GEMM + bias + ReLU: H[n,d] = relu(sum_k V[n,k]*W[d,k] + b[d])
// Block: 256 threads, tile 32 nodes x 128 dims, 4x4 register blocking.
// ---------------------------------------------------------------------------
__global__ __launch_bounds__(256) void gemm_relu_kernel(
    const float* __restrict__ V, const float* __restrict__ W,
    const float* __restrict__ b, float* __restrict__ H) {
    __shared__ float Vs[32][128];      // [node][k], reads are warp-broadcast
    __shared__ float Ws[128][33];      // [d][k-tile], padded (2-way read conflict)

    const int tid = threadIdx.x;
    const int tx  = tid & 31;          // d-group: dims [4*tx, 4*tx+3]
    const int ty  = tid >> 5;          // n-group: nodes [4*ty, 4*ty+3]
    const int n0  = blockIdx.x * 32;

    // Load V tile (full K): 4096 floats, coalesced.
    #pragma unroll
    for (int j = 0; j < 16; j++) {
        int i = tid + j * 256;
        int n = i >> 7;
        int k = i & 127;
        int node = n0 + n;
        Vs[n][k] = (node < N_NODES) ? V[node * DIM + k] : 0.f;
    }

    float acc[4][4];
    #pragma unroll
    for (int a = 0; a < 4; a++)
        #pragma unroll
        for (int c = 0; c < 4; c++) acc[a][c] = 0.f;

    for (int k0 = 0; k0 < DIM; k0 += 32) {
        __syncthreads();
        // Load W tile: 128 d x 32 k, coalesced global reads.
        #pragma unroll
        for (int j = 0; j < 16; j++) {
            int i  = tid + j * 256;
            int dd = i >> 5;
            int kk = i & 31;
            Ws[dd][kk] = W[dd * DIM + k0 + kk];
        }
        __syncthreads();

        #pragma unroll
        for (int kk = 0; kk < 32; kk++) {
            float wv[4], vv[4];
            #pragma unroll
            for (int c = 0; c < 4; c++) wv[c] = Ws[tx * 4 + c][kk];
            #pragma unroll
            for (int a = 0; a < 4; a++) vv[a] = Vs[ty * 4 + a][k0 + kk];
            #pragma unroll
            for (int a = 0; a < 4; a++)
                #pragma unroll
                for (int c = 0; c < 4; c++) acc[a][c] += vv[a] * wv[c];
        }
    }

    // bias + relu + store (float4, coalesced across tx)
    const int d0 = tx * 4;
    float4 bv = *(const float4*)(b + d0);
    #pragma unroll
    for (int a = 0; a < 4; a++) {
        int node = n0 + ty * 4 + a;
        if (node < N_NODES) {
            float4 o;
            o.x = fmaxf(acc[a][0] + bv.x, 0.f);
            o.y = fmaxf(acc[a][1] + bv.y, 0.f);
            o.z = fmaxf(acc[a][2] + bv.z, 0.f);
            o.w = fmaxf(acc[a][3] + bv.w, 0.f);
            *(float4*)(H + node * DIM + d0) = o;
        }
    }
}

// ---------------------------------------------------------------------------
// Scatter-max: one warp per edge. Each lane handles 4 dims (float4 gather).
// H >= 0, so integer atomicMax on float bits is order-preserving and the
// h > 0 predicate skips ~half the atomics (ReLU zeros are no-ops vs init 0).
// ---------------------------------------------------------------------------
__global__ __launch_bounds__(256) void scatter_max_kernel(
    const void* __restrict__ srcp, const void* __restrict__ dstp,
    const float* __restrict__ H, float* __restrict__ out) {
    const int e = blockIdx.x * 8 + (threadIdx.x >> 5);
    if (e >= N_EDGES) return;
    const int lane = threadIdx.x & 31;

    long long s, d;
    if (g_idx32) {
        s = ((const int*)srcp)[e];
        d = ((const int*)dstp)[e];
    } else {
        s = ((const long long*)srcp)[e];
        d = ((const long long*)dstp)[e];
    }

    float4 h = *(const float4*)(H + s * DIM + lane * 4);
    int* o = (int*)(out + d * DIM + lane * 4);
    if (h.x > 0.f) atomicMax(o + 0, __float_as_int(h.x));
    if (h.y > 0.f) atomicMax(o + 1, __float_as_int(h.y));
    if (h.z > 0.f) atomicMax(o + 2, __float_as_int(h.z));
    if (h.w > 0.f) atomicMax(o + 3, __float_as_int(h.w));
}

// ---------------------------------------------------------------------------
extern "C" void kernel_launch(void* const* d_in, const int* in_sizes, int n_in,
                              void* d_out, int out_size) {
    const float* V   = (const float*)d_in[0];
    const float* W   = (const float*)d_in[1];
    const float* b   = (const float*)d_in[2];
    const void*  src = d_in[3];
    const void*  dst = d_in[4];
    float* out = (float*)d_out;

    float* H;
    cudaGetSymbolAddress((void**)&H, g_H);

    detect_idx_dtype<<<1, 256>>>((const unsigned int*)src);
    zero_out_kernel<<<(N_NODES * (DIM / 4) + 255) / 256, 256>>>((float4*)out);
    gemm_relu_kernel<<<(N_NODES + 31) / 32, 256>>>(V, W, b, H);
    scatter_max_kernel<<<(N_EDGES + 7) / 8, 256>>>(src, dst, H, out);
}

// round 2
// speedup vs baseline: 1.6684x; 1.6684x over previous
#include <cuda_runtime.h>
#include <cuda_bf16.h>
#include <cstdint>

#define N_NODES 50000
#define N_EDGES 800000
#define DIM 128

// ---------------------------------------------------------------------------
// Device scratch (static allocation is allowed; cudaMalloc is not)
// ---------------------------------------------------------------------------
__device__ float g_H[N_NODES * DIM];        // H = relu(V @ W^T + b)
__device__ int   g_deg[N_NODES];            // in-degree histogram
__device__ int   g_offs[N_NODES + 1];       // CSR row offsets (by dst)
__device__ int   g_cursor[N_NODES];         // fill cursors
__device__ int   g_csr_src[N_EDGES];        // CSR column indices (src node)
__device__ int   g_idx32;                   // 1 if indices are int32

// ---------------------------------------------------------------------------
// Detect index dtype: int64 indices < 50000 have all-zero high 32-bit words.
// ---------------------------------------------------------------------------
__global__ void detect_idx_dtype(const unsigned int* __restrict__ srcw) {
    __shared__ int found;
    if (threadIdx.x == 0) found = 0;
    __syncthreads();
    for (int i = threadIdx.x; i < 2048; i += blockDim.x)
        if (srcw[2 * i + 1] != 0u) found = 1;
    __syncthreads();
    if (threadIdx.x == 0) g_idx32 = found;
}

__device__ __forceinline__ int load_idx(const void* p, int e) {
    return g_idx32 ? ((const int*)p)[e] : (int)((const long long*)p)[e];
}

// ---------------------------------------------------------------------------
// CSR build: zero degrees -> histogram -> scan -> fill
// ---------------------------------------------------------------------------
__global__ void zero_deg_kernel() {
    int i = blockIdx.x * blockDim.x + threadIdx.x;
    if (i < N_NODES) g_deg[i] = 0;
}

__global__ __launch_bounds__(256) void hist_kernel(const void* __restrict__ dstp) {
    int e = blockIdx.x * blockDim.x + threadIdx.x;
    if (e >= N_EDGES) return;
    atomicAdd(&g_deg[load_idx(dstp, e)], 1);
}

// Single-block exclusive scan over 50000 ints (two-pass per thread chunk).
__global__ __launch_bounds__(1024) void scan_kernel() {
    __shared__ int part[1024];
    const int t = threadIdx.x;
    const int CH = 49;                      // 1024 * 49 = 50176 >= 50000
    const int base = t * CH;

    int s = 0;
    for (int j = 0; j < CH; j++) {
        int i = base + j;
        if (i < N_NODES) s += g_deg[i];
    }
    part[t] = s;
    __syncthreads();
    // Hillis-Steele inclusive scan
    for (int off = 1; off < 1024; off <<= 1) {
        int v = (t >= off) ? part[t - off] : 0;
        __syncthreads();
        part[t] += v;
        __syncthreads();
    }
    int run = (t > 0) ? part[t - 1] : 0;    // exclusive prefix of this chunk
    for (int j = 0; j < CH; j++) {
        int i = base + j;
        if (i < N_NODES) {
            g_offs[i]   = run;
            g_cursor[i] = run;
            run += g_deg[i];
        }
    }
    if (t == 1023) g_offs[N_NODES] = part[1023];
}

__global__ __launch_bounds__(256) void fill_kernel(const void* __restrict__ srcp,
                                                   const void* __restrict__ dstp) {
    int e = blockIdx.x * blockDim.x + threadIdx.x;
    if (e >= N_EDGES) return;
    int s = load_idx(srcp, e);
    int d = load_idx(dstp, e);
    int p = atomicAdd(&g_cursor[d], 1);
    g_csr_src[p] = s;
}

// ---------------------------------------------------------------------------
// GEMM + bias + ReLU using packed fma.rn.f32x2, paired along K.
//   acc.x accumulates even-k products, acc.y odd-k; final result = .x + .y.
//   Both v (V[n][2k..2k+1]) and w (W[d][2k..2k+1]) are contiguous 8B in the
//   NATURAL layouts -> no smem transposes. v is lane-invariant (broadcast).
// Block: 256 threads, tile 64 nodes x 128 dims.
//   warp ty handles nodes [ty*8, ty*8+8); lane tx handles dims {tx+32c}.
// ---------------------------------------------------------------------------
#define GEMM_SMEM_BYTES ((64 * 132 + 128 * 128) * 4)

__device__ __forceinline__ void ffma2(unsigned long long& acc,
                                      unsigned long long a,
                                      unsigned long long b) {
    asm("fma.rn.f32x2 %0, %1, %2, %0;" : "+l"(acc) : "l"(a), "l"(b));
}

__global__ __launch_bounds__(256) void gemm_relu_kernel(
    const float* __restrict__ V, const float* __restrict__ W,
    const float* __restrict__ b, float* __restrict__ H) {
    extern __shared__ float smem[];
    float* Vs = smem;                 // [64][132]  (132: float4-aligned pad)
    float* Ws = smem + 64 * 132;      // [128][128] column-swizzled by (d&15)

    const int tid = threadIdx.x;
    const int tx  = tid & 31;
    const int ty  = tid >> 5;
    const int n0  = blockIdx.x * 64;

    // Load V tile: 64 rows x 128 cols, float4 coalesced.
    #pragma unroll
    for (int j = 0; j < 8; j++) {
        int f = tid + j * 256;        // float4 index
        int n = f >> 5;
        int c4 = (f & 31) << 2;
        int node = n0 + n;
        float4 v = (node < N_NODES) ? *(const float4*)(V + node * DIM + c4)
                                    : make_float4(0.f, 0.f, 0.f, 0.f);
        *(float4*)(Vs + n * 132 + c4) = v;
    }
    // Load W (full 128x128) as float2 with column swizzle: k2' = k2 ^ (d&15).
    #pragma unroll
    for (int j = 0; j < 32; j++) {
        int p  = tid + j * 256;       // float2 index
        int d  = p >> 6;
        int k2 = p & 63;
        float2 w = *(const float2*)(W + d * DIM + (k2 << 1));
        *(float2*)(Ws + d * DIM + ((k2 ^ (d & 15)) << 1)) = w;
    }
    __syncthreads();

    unsigned long long acc[8][4];
    #pragma unroll
    for (int a = 0; a < 8; a++)
        #pragma unroll
        for (int c = 0; c < 4; c++) acc[a][c] = 0ull;

    const int sw = tx & 15;           // swizzle key, constant across c
    #pragma unroll 4
    for (int k2 = 0; k2 < 64; k2++) {
        unsigned long long wv[4];
        const int kw = ((k2 ^ sw) << 1);
        #pragma unroll
        for (int c = 0; c < 4; c++)
            wv[c] = *(const unsigned long long*)(Ws + (tx + 32 * c) * DIM + kw);
        unsigned long long vv[8];
        #pragma unroll
        for (int a = 0; a < 8; a++)
            vv[a] = *(const unsigned long long*)(Vs + (ty * 8 + a) * 132 + (k2 << 1));
        #pragma unroll
        for (int a = 0; a < 8; a++)
            #pragma unroll
            for (int c = 0; c < 4; c++) ffma2(acc[a][c], vv[a], wv[c]);
    }

    // Horizontal add + bias + relu + store (coalesced across tx per c).
    float bv[4];
    #pragma unroll
    for (int c = 0; c < 4; c++) bv[c] = b[tx + 32 * c];
    #pragma unroll
    for (int a = 0; a < 8; a++) {
        int node = n0 + ty * 8 + a;
        if (node < N_NODES) {
            #pragma unroll
            for (int c = 0; c < 4; c++) {
                float2 f = *reinterpret_cast<float2*>(&acc[a][c]);
                float r = f.x + f.y + bv[c];
                H[node * DIM + tx + 32 * c] = fmaxf(r, 0.f);
            }
        }
    }
}

// ---------------------------------------------------------------------------
// Aggregate: one warp per dst node, max over CSR in-edges, no atomics.
// Each lane owns 4 dims (float4). Writes every node (0 if no edges).
// ---------------------------------------------------------------------------
__global__ __launch_bounds__(256) void aggregate_kernel(
    const float* __restrict__ H, float* __restrict__ out) {
    const int node = blockIdx.x * 8 + (threadIdx.x >> 5);
    if (node >= N_NODES) return;
    const int lane = threadIdx.x & 31;

    const int beg = g_offs[node];
    const int end = g_offs[node + 1];
    const float4* __restrict__ H4 = (const float4*)H;

    float4 m = make_float4(0.f, 0.f, 0.f, 0.f);
    int j = beg;
    for (; j + 4 <= end; j += 4) {
        int s0 = g_csr_src[j],     s1 = g_csr_src[j + 1];
        int s2 = g_csr_src[j + 2], s3 = g_csr_src[j + 3];
        float4 h0 = H4[s0 * 32 + lane];
        float4 h1 = H4[s1 * 32 + lane];
        float4 h2 = H4[s2 * 32 + lane];
        float4 h3 = H4[s3 * 32 + lane];
        m.x = fmaxf(fmaxf(m.x, h0.x), fmaxf(h1.x, fmaxf(h2.x, h3.x)));
        m.y = fmaxf(fmaxf(m.y, h0.y), fmaxf(h1.y, fmaxf(h2.y, h3.y)));
        m.z = fmaxf(fmaxf(m.z, h0.z), fmaxf(h1.z, fmaxf(h2.z, h3.z)));
        m.w = fmaxf(fmaxf(m.w, h0.w), fmaxf(h1.w, fmaxf(h2.w, h3.w)));
    }
    for (; j < end; j++) {
        int s = g_csr_src[j];
        float4 h = H4[s * 32 + lane];
        m.x = fmaxf(m.x, h.x); m.y = fmaxf(m.y, h.y);
        m.z = fmaxf(m.z, h.z); m.w = fmaxf(m.w, h.w);
    }
    ((float4*)out)[node * 32 + lane] = m;
}

// ---------------------------------------------------------------------------
extern "C" void kernel_launch(void* const* d_in, const int* in_sizes, int n_in,
                              void* d_out, int out_size) {
    const float* V   = (const float*)d_in[0];
    const float* W   = (const float*)d_in[1];
    const float* b   = (const float*)d_in[2];
    const void*  src = d_in[3];
    const void*  dst = d_in[4];
    float* out = (float*)d_out;

    float* H;
    cudaGetSymbolAddress((void**)&H, g_H);

    cudaFuncSetAttribute(gemm_relu_kernel,
                         cudaFuncAttributeMaxDynamicSharedMemorySize,
                         GEMM_SMEM_BYTES);

    detect_idx_dtype<<<1, 256>>>((const unsigned int*)src);
    zero_deg_kernel<<<(N_NODES + 255) / 256, 256>>>();
    gemm_relu_kernel<<<(N_NODES + 63) / 64, 256, GEMM_SMEM_BYTES>>>(V, W, b, H);
    hist_kernel<<<(N_EDGES + 255) / 256, 256>>>(dst);
    scan_kernel<<<1, 1024>>>();
    fill_kernel<<<(N_EDGES + 255) / 256, 256>>>(src, dst);
    aggregate_kernel<<<(N_NODES + 7) / 8, 256>>>(H, out);
}

// round 3
// speedup vs baseline: 2.5769x; 1.5446x over previous
#include <cuda_runtime.h>
#include <cuda_bf16.h>
#include <cstdint>

#define N_NODES 50000
#define N_EDGES 800000
#define DIM 128
#define N_PAD 53248               // 1024 * 52, int4-friendly padding

// ---------------------------------------------------------------------------
// Device scratch
// ---------------------------------------------------------------------------
__device__ float g_H[N_NODES * DIM];                 // relu(V @ W^T + b)
__device__ __align__(16) int g_deg[N_PAD];           // in-degree histogram
__device__ __align__(16) int g_offs[N_PAD + 4];      // CSR row offsets (by dst)
__device__ __align__(16) int g_cursor[N_PAD];        // fill cursors
__device__ int g_csr_src[N_EDGES];                   // CSR columns (src node)
__device__ int g_idx32;                              // 1 if indices are int32

// ---------------------------------------------------------------------------
// prep: zero padded degree array; block 0 also detects index dtype
// (int64 indices < 50000 have all-zero high 32-bit words).
// ---------------------------------------------------------------------------
__global__ void prep_kernel(const unsigned int* __restrict__ srcw) {
    int i = blockIdx.x * blockDim.x + threadIdx.x;
    if (i < N_PAD) g_deg[i] = 0;
    if (blockIdx.x == 0) {
        __shared__ int found;
        if (threadIdx.x == 0) found = 0;
        __syncthreads();
        for (int j = threadIdx.x; j < 2048; j += blockDim.x)
            if (srcw[2 * j + 1] != 0u) found = 1;
        __syncthreads();
        if (threadIdx.x == 0) g_idx32 = found;
    }
}

__device__ __forceinline__ int load_idx(const void* p, int e) {
    return g_idx32 ? ((const int*)p)[e] : (int)((const long long*)p)[e];
}

__global__ __launch_bounds__(256) void hist_kernel(const void* __restrict__ dstp) {
    int e = blockIdx.x * blockDim.x + threadIdx.x;
    if (e >= N_EDGES) return;
    atomicAdd(&g_deg[load_idx(dstp, e)], 1);
}

// ---------------------------------------------------------------------------
// Single-block exclusive scan over N_PAD ints. Two-phase per-thread chunk of
// 52 (13x int4): phase 1 sums, phase 2 reloads (L1-warm) and writes prefixes.
// Padded tail degrees are 0, so offs[50000] = total edge count automatically.
// ---------------------------------------------------------------------------
__global__ __launch_bounds__(1024) void scan_kernel() {
    __shared__ int part[1024];
    const int t = threadIdx.x;
    const int4* dp = (const int4*)(g_deg + t * 52);

    int s = 0;
    #pragma unroll
    for (int j = 0; j < 13; j++) {
        int4 x = dp[j];
        s += x.x + x.y + x.z + x.w;
    }
    part[t] = s;
    __syncthreads();
    // Hillis-Steele inclusive scan over 1024 partials
    for (int off = 1; off < 1024; off <<= 1) {
        int v = (t >= off) ? part[t - off] : 0;
        __syncthreads();
        part[t] += v;
        __syncthreads();
    }
    int run = (t > 0) ? part[t - 1] : 0;

    int4* op = (int4*)(g_offs + t * 52);
    int4* cp = (int4*)(g_cursor + t * 52);
    #pragma unroll
    for (int j = 0; j < 13; j++) {
        int4 x = dp[j];
        int4 o;
        o.x = run; run += x.x;
        o.y = run; run += x.y;
        o.z = run; run += x.z;
        o.w = run; run += x.w;
        op[j] = o;
        cp[j] = o;
    }
}

__global__ __launch_bounds__(256) void fill_kernel(const void* __restrict__ srcp,
                                                   const void* __restrict__ dstp) {
    int e = blockIdx.x * blockDim.x + threadIdx.x;
    if (e >= N_EDGES) return;
    int s = load_idx(srcp, e);
    int d = load_idx(dstp, e);
    int p = atomicAdd(&g_cursor[d], 1);
    g_csr_src[p] = s;
}

// ---------------------------------------------------------------------------
// GEMM + bias + ReLU using packed fma.rn.f32x2, paired along K.
// ---------------------------------------------------------------------------
#define GEMM_SMEM_BYTES ((64 * 132 + 128 * 128) * 4)

__device__ __forceinline__ void ffma2(unsigned long long& acc,
                                      unsigned long long a,
                                      unsigned long long b) {
    asm("fma.rn.f32x2 %0, %1, %2, %0;" : "+l"(acc) : "l"(a), "l"(b));
}

__global__ __launch_bounds__(256) void gemm_relu_kernel(
    const float* __restrict__ V, const float* __restrict__ W,
    const float* __restrict__ b, float* __restrict__ H) {
    extern __shared__ float smem[];
    float* Vs = smem;                 // [64][132]
    float* Ws = smem + 64 * 132;      // [128][128], column-swizzled by (d&15)

    const int tid = threadIdx.x;
    const int tx  = tid & 31;
    const int ty  = tid >> 5;
    const int n0  = blockIdx.x * 64;

    #pragma unroll
    for (int j = 0; j < 8; j++) {
        int f = tid + j * 256;
        int n = f >> 5;
        int c4 = (f & 31) << 2;
        int node = n0 + n;
        float4 v = (node < N_NODES) ? *(const float4*)(V + node * DIM + c4)
                                    : make_float4(0.f, 0.f, 0.f, 0.f);
        *(float4*)(Vs + n * 132 + c4) = v;
    }
    #pragma unroll
    for (int j = 0; j < 32; j++) {
        int p  = tid + j * 256;
        int d  = p >> 6;
        int k2 = p & 63;
        float2 w = *(const float2*)(W + d * DIM + (k2 << 1));
        *(float2*)(Ws + d * DIM + ((k2 ^ (d & 15)) << 1)) = w;
    }
    __syncthreads();

    unsigned long long acc[8][4];
    #pragma unroll
    for (int a = 0; a < 8; a++)
        #pragma unroll
        for (int c = 0; c < 4; c++) acc[a][c] = 0ull;

    const int sw = tx & 15;
    #pragma unroll 4
    for (int k2 = 0; k2 < 64; k2++) {
        unsigned long long wv[4];
        const int kw = ((k2 ^ sw) << 1);
        #pragma unroll
        for (int c = 0; c < 4; c++)
            wv[c] = *(const unsigned long long*)(Ws + (tx + 32 * c) * DIM + kw);
        unsigned long long vv[8];
        #pragma unroll
        for (int a = 0; a < 8; a++)
            vv[a] = *(const unsigned long long*)(Vs + (ty * 8 + a) * 132 + (k2 << 1));
        #pragma unroll
        for (int a = 0; a < 8; a++)
            #pragma unroll
            for (int c = 0; c < 4; c++) ffma2(acc[a][c], vv[a], wv[c]);
    }

    float bv[4];
    #pragma unroll
    for (int c = 0; c < 4; c++) bv[c] = b[tx + 32 * c];
    #pragma unroll
    for (int a = 0; a < 8; a++) {
        int node = n0 + ty * 8 + a;
        if (node < N_NODES) {
            #pragma unroll
            for (int c = 0; c < 4; c++) {
                float2 f = *reinterpret_cast<float2*>(&acc[a][c]);
                float r = f.x + f.y + bv[c];
                H[node * DIM + tx + 32 * c] = fmaxf(r, 0.f);
            }
        }
    }
}

// ---------------------------------------------------------------------------
// Aggregate: one warp per dst node, max over CSR in-edges, no atomics.
// ---------------------------------------------------------------------------
__global__ __launch_bounds__(256) void aggregate_kernel(
    const float* __restrict__ H, float* __restrict__ out) {
    const int node = blockIdx.x * 8 + (threadIdx.x >> 5);
    if (node >= N_NODES) return;
    const int lane = threadIdx.x & 31;

    const int beg = g_offs[node];
    const int end = g_offs[node + 1];
    const float4* __restrict__ H4 = (const float4*)H;

    float4 m = make_float4(0.f, 0.f, 0.f, 0.f);
    int j = beg;
    for (; j + 4 <= end; j += 4) {
        int s0 = g_csr_src[j],     s1 = g_csr_src[j + 1];
        int s2 = g_csr_src[j + 2], s3 = g_csr_src[j + 3];
        float4 h0 = H4[s0 * 32 + lane];
        float4 h1 = H4[s1 * 32 + lane];
        float4 h2 = H4[s2 * 32 + lane];
        float4 h3 = H4[s3 * 32 + lane];
        m.x = fmaxf(fmaxf(m.x, h0.x), fmaxf(h1.x, fmaxf(h2.x, h3.x)));
        m.y = fmaxf(fmaxf(m.y, h0.y), fmaxf(h1.y, fmaxf(h2.y, h3.y)));
        m.z = fmaxf(fmaxf(m.z, h0.z), fmaxf(h1.z, fmaxf(h2.z, h3.z)));
        m.w = fmaxf(fmaxf(m.w, h0.w), fmaxf(h1.w, fmaxf(h2.w, h3.w)));
    }
    for (; j < end; j++) {
        int s = g_csr_src[j];
        float4 h = H4[s * 32 + lane];
        m.x = fmaxf(m.x, h.x); m.y = fmaxf(m.y, h.y);
        m.z = fmaxf(m.z, h.z); m.w = fmaxf(m.w, h.w);
    }
    ((float4*)out)[node * 32 + lane] = m;
}

// ---------------------------------------------------------------------------
extern "C" void kernel_launch(void* const* d_in, const int* in_sizes, int n_in,
                              void* d_out, int out_size) {
    const float* V   = (const float*)d_in[0];
    const float* W   = (const float*)d_in[1];
    const float* b   = (const float*)d_in[2];
    const void*  src = d_in[3];
    const void*  dst = d_in[4];
    float* out = (float*)d_out;

    float* H;
    cudaGetSymbolAddress((void**)&H, g_H);

    // Host-side resources, created once (no device memory involved).
    static cudaStream_t s_gemm = nullptr;
    static cudaEvent_t ev_fork = nullptr, ev_gemm = nullptr;
    if (!s_gemm) {
        cudaStreamCreateWithFlags(&s_gemm, cudaStreamNonBlocking);
        cudaEventCreateWithFlags(&ev_fork, cudaEventDisableTiming);
        cudaEventCreateWithFlags(&ev_gemm, cudaEventDisableTiming);
        cudaFuncSetAttribute(gemm_relu_kernel,
                             cudaFuncAttributeMaxDynamicSharedMemorySize,
                             GEMM_SMEM_BYTES);
    }

    // Fork: GEMM (V,W,b -> H) runs concurrently with the CSR build (src,dst).
    cudaEventRecord(ev_fork, 0);
    cudaStreamWaitEvent(s_gemm, ev_fork, 0);
    gemm_relu_kernel<<<(N_NODES + 63) / 64, 256, GEMM_SMEM_BYTES, s_gemm>>>(V, W, b, H);
    cudaEventRecord(ev_gemm, s_gemm);

    prep_kernel<<<(N_PAD + 255) / 256, 256>>>((const unsigned int*)src);
    hist_kernel<<<(N_EDGES + 255) / 256, 256>>>(dst);
    scan_kernel<<<1, 1024>>>();
    fill_kernel<<<(N_EDGES + 255) / 256, 256>>>(src, dst);

    // Join: aggregate needs both H and the CSR.
    cudaStreamWaitEvent(0, ev_gemm, 0);
    aggregate_kernel<<<(N_NODES + 7) / 8, 256>>>(H, out);
}

// round 4
// speedup vs baseline: 3.1171x; 1.2096x over previous
#include <cuda_runtime.h>
#include <cuda_bf16.h>
#include <cstdint>

#define N_NODES 50000
#define N_EDGES 800000
#define DIM 128
#define N_PAD 53248               // 52 * 1024
#define N_PART 52

// ---------------------------------------------------------------------------
// Device scratch
// ---------------------------------------------------------------------------
__device__ float g_H[N_NODES * DIM];                 // relu(V @ W^T + b)
__device__ __align__(16) int g_deg[N_PAD];           // in-degree histogram
__device__ __align__(16) int g_offs[N_PAD + 4];      // CSR row offsets (by dst)
__device__ __align__(16) int g_cursor[N_PAD];        // fill cursors
__device__ int g_csr_src[N_EDGES];                   // CSR columns (src node)
__device__ int g_part[64];                           // block partial sums
__device__ int g_bsum[64];                           // exclusive block prefixes
__device__ int g_idx32;                              // 1 if indices are int32

// ---------------------------------------------------------------------------
// prep: zero padded degree array; block 0 also detects index dtype
// (int64 indices < 50000 have all-zero high 32-bit words).
// ---------------------------------------------------------------------------
__global__ void prep_kernel(const unsigned int* __restrict__ srcw) {
    int i = blockIdx.x * blockDim.x + threadIdx.x;
    if (i < N_PAD) g_deg[i] = 0;
    if (blockIdx.x == 0) {
        __shared__ int found;
        if (threadIdx.x == 0) found = 0;
        __syncthreads();
        for (int j = threadIdx.x; j < 2048; j += blockDim.x)
            if (srcw[2 * j + 1] != 0u) found = 1;
        __syncthreads();
        if (threadIdx.x == 0) g_idx32 = found;
    }
}

__device__ __forceinline__ int load_idx(const void* p, int e) {
    return g_idx32 ? ((const int*)p)[e] : (int)((const long long*)p)[e];
}

__global__ __launch_bounds__(256) void hist_kernel(const void* __restrict__ dstp) {
    int e = blockIdx.x * blockDim.x + threadIdx.x;
    if (e >= N_EDGES) return;
    atomicAdd(&g_deg[load_idx(dstp, e)], 1);
}

// ---------------------------------------------------------------------------
// Parallel scan, 3 phases.
// ---------------------------------------------------------------------------
// Phase 1: per-block (1024 ints) partial sums.
__global__ __launch_bounds__(1024) void scan1_kernel() {
    __shared__ int wsum[32];
    const int t = threadIdx.x, lane = t & 31, wid = t >> 5;
    int v = g_deg[blockIdx.x * 1024 + t];
    #pragma unroll
    for (int o = 16; o > 0; o >>= 1) v += __shfl_down_sync(~0u, v, o);
    if (lane == 0) wsum[wid] = v;
    __syncthreads();
    if (wid == 0) {
        int s = wsum[lane];
        #pragma unroll
        for (int o = 16; o > 0; o >>= 1) s += __shfl_down_sync(~0u, s, o);
        if (lane == 0) g_part[blockIdx.x] = s;
    }
}

// Phase 2: exclusive scan of 52 partials (one tiny block).
__global__ void scan2_kernel() {
    __shared__ int sm[64];
    const int t = threadIdx.x;
    sm[t] = (t < N_PART) ? g_part[t] : 0;
    __syncthreads();
    #pragma unroll
    for (int off = 1; off < 64; off <<= 1) {
        int v = (t >= off) ? sm[t - off] : 0;
        __syncthreads();
        sm[t] += v;
        __syncthreads();
    }
    if (t < N_PART) g_bsum[t] = sm[t] - g_part[t];  // exclusive
}

// Phase 3: per-block exclusive scan + block offset -> offs & cursor.
__global__ __launch_bounds__(1024) void scan3_kernel() {
    __shared__ int wsum[33];
    const int t = threadIdx.x, lane = t & 31, wid = t >> 5;
    const int i = blockIdx.x * 1024 + t;
    int v = g_deg[i];
    int x = v;
    #pragma unroll
    for (int o = 1; o < 32; o <<= 1) {
        int y = __shfl_up_sync(~0u, x, o);
        if (lane >= o) x += y;
    }
    if (lane == 31) wsum[wid + 1] = x;
    __syncthreads();
    if (wid == 0) {
        int s = (lane < 31) ? wsum[lane + 1] : 0;
        // inclusive scan of 31 warp sums shifted -> exclusive warp offsets
        #pragma unroll
        for (int o = 1; o < 32; o <<= 1) {
            int y = __shfl_up_sync(~0u, s, o);
            if (lane >= o) s += y;
        }
        wsum[lane + 1] = s;
        if (lane == 0) wsum[0] = 0;
    }
    __syncthreads();
    int excl = (x - v) + wsum[wid] + g_bsum[blockIdx.x];
    g_offs[i] = excl;
    g_cursor[i] = excl;
}

__global__ __launch_bounds__(256) void fill_kernel(const void* __restrict__ srcp,
                                                   const void* __restrict__ dstp) {
    int e = blockIdx.x * blockDim.x + threadIdx.x;
    if (e >= N_EDGES) return;
    int s = load_idx(srcp, e);
    int d = load_idx(dstp, e);
    int p = atomicAdd(&g_cursor[d], 1);
    g_csr_src[p] = s;
}

// ---------------------------------------------------------------------------
// GEMM + bias + ReLU using packed fma.rn.f32x2, k in quads via LDS.128.
// Block: 256 threads, tile 64 nodes x 128 dims, 2 blocks/SM.
// ---------------------------------------------------------------------------
#define GEMM_SMEM_BYTES ((64 * 132 + 128 * 128) * 4)

__device__ __forceinline__ void ffma2(unsigned long long& acc,
                                      unsigned long long a,
                                      unsigned long long b) {
    asm("fma.rn.f32x2 %0, %1, %2, %0;" : "+l"(acc) : "l"(a), "l"(b));
}

__global__ __launch_bounds__(256, 2) void gemm_relu_kernel(
    const float* __restrict__ V, const float* __restrict__ W,
    const float* __restrict__ b, float* __restrict__ H) {
    extern __shared__ float smem[];
    float* Vs = smem;                 // [64][132]
    float* Ws = smem + 64 * 132;      // [128][128], float4-col swizzle by (d&31)

    const int tid = threadIdx.x;
    const int tx  = tid & 31;
    const int ty  = tid >> 5;
    const int n0  = blockIdx.x * 64;

    // V tile: 64 x 128, float4 coalesced.
    #pragma unroll
    for (int j = 0; j < 8; j++) {
        int f = tid + j * 256;
        int n = f >> 5;
        int c4 = (f & 31) << 2;
        int node = n0 + n;
        float4 v = (node < N_NODES) ? *(const float4*)(V + node * DIM + c4)
                                    : make_float4(0.f, 0.f, 0.f, 0.f);
        *(float4*)(Vs + n * 132 + c4) = v;
    }
    // W (128x128) as float4, column-swizzled: c4' = c4 ^ (d & 31).
    #pragma unroll
    for (int j = 0; j < 16; j++) {
        int p  = tid + j * 256;
        int d  = p >> 5;
        int c4 = p & 31;
        float4 w = *(const float4*)(W + d * DIM + (c4 << 2));
        *(float4*)(Ws + d * DIM + ((c4 ^ (d & 31)) << 2)) = w;
    }
    __syncthreads();

    unsigned long long acc[8][4];
    #pragma unroll
    for (int a = 0; a < 8; a++)
        #pragma unroll
        for (int c = 0; c < 4; c++) acc[a][c] = 0ull;

    #pragma unroll 2
    for (int k4 = 0; k4 < 32; k4++) {
        ulonglong2 wv[4];
        const int kw = ((k4 ^ tx) << 2);
        #pragma unroll
        for (int c = 0; c < 4; c++)
            wv[c] = *(const ulonglong2*)(Ws + (tx + 32 * c) * DIM + kw);
        ulonglong2 vv[8];
        #pragma unroll
        for (int a = 0; a < 8; a++)
            vv[a] = *(const ulonglong2*)(Vs + (ty * 8 + a) * 132 + (k4 << 2));
        #pragma unroll
        for (int a = 0; a < 8; a++)
            #pragma unroll
            for (int c = 0; c < 4; c++) {
                ffma2(acc[a][c], vv[a].x, wv[c].x);
                ffma2(acc[a][c], vv[a].y, wv[c].y);
            }
    }

    float bv[4];
    #pragma unroll
    for (int c = 0; c < 4; c++) bv[c] = b[tx + 32 * c];
    #pragma unroll
    for (int a = 0; a < 8; a++) {
        int node = n0 + ty * 8 + a;
        if (node < N_NODES) {
            #pragma unroll
            for (int c = 0; c < 4; c++) {
                float2 f = *reinterpret_cast<float2*>(&acc[a][c]);
                float r = f.x + f.y + bv[c];
                H[node * DIM + tx + 32 * c] = fmaxf(r, 0.f);
            }
        }
    }
}

// ---------------------------------------------------------------------------
// Aggregate: one warp per dst node, 8-deep gather batches, no atomics.
// ---------------------------------------------------------------------------
__global__ __launch_bounds__(256) void aggregate_kernel(
    const float* __restrict__ H, float* __restrict__ out) {
    const int node = blockIdx.x * 8 + (threadIdx.x >> 5);
    if (node >= N_NODES) return;
    const int lane = threadIdx.x & 31;

    const int beg = g_offs[node];
    const int end = g_offs[node + 1];
    const float4* __restrict__ H4 = (const float4*)H;

    float4 m = make_float4(0.f, 0.f, 0.f, 0.f);
    int j = beg;
    for (; j + 8 <= end; j += 8) {
        int s[8];
        #pragma unroll
        for (int u = 0; u < 8; u++) s[u] = g_csr_src[j + u];
        float4 h[8];
        #pragma unroll
        for (int u = 0; u < 8; u++) h[u] = H4[s[u] * 32 + lane];
        #pragma unroll
        for (int u = 0; u < 8; u++) {
            m.x = fmaxf(m.x, h[u].x); m.y = fmaxf(m.y, h[u].y);
            m.z = fmaxf(m.z, h[u].z); m.w = fmaxf(m.w, h[u].w);
        }
    }
    if (j + 4 <= end) {
        int s[4];
        #pragma unroll
        for (int u = 0; u < 4; u++) s[u] = g_csr_src[j + u];
        float4 h[4];
        #pragma unroll
        for (int u = 0; u < 4; u++) h[u] = H4[s[u] * 32 + lane];
        #pragma unroll
        for (int u = 0; u < 4; u++) {
            m.x = fmaxf(m.x, h[u].x); m.y = fmaxf(m.y, h[u].y);
            m.z = fmaxf(m.z, h[u].z); m.w = fmaxf(m.w, h[u].w);
        }
        j += 4;
    }
    for (; j < end; j++) {
        float4 h = H4[g_csr_src[j] * 32 + lane];
        m.x = fmaxf(m.x, h.x); m.y = fmaxf(m.y, h.y);
        m.z = fmaxf(m.z, h.z); m.w = fmaxf(m.w, h.w);
    }
    ((float4*)out)[node * 32 + lane] = m;
}

// ---------------------------------------------------------------------------
extern "C" void kernel_launch(void* const* d_in, const int* in_sizes, int n_in,
                              void* d_out, int out_size) {
    const float* V   = (const float*)d_in[0];
    const float* W   = (const float*)d_in[1];
    const float* b   = (const float*)d_in[2];
    const void*  src = d_in[3];
    const void*  dst = d_in[4];
    float* out = (float*)d_out;

    float* H;
    cudaGetSymbolAddress((void**)&H, g_H);

    static cudaStream_t s_gemm = nullptr;
    static cudaEvent_t ev_fork = nullptr, ev_gemm = nullptr;
    if (!s_gemm) {
        cudaStreamCreateWithFlags(&s_gemm, cudaStreamNonBlocking);
        cudaEventCreateWithFlags(&ev_fork, cudaEventDisableTiming);
        cudaEventCreateWithFlags(&ev_gemm, cudaEventDisableTiming);
        cudaFuncSetAttribute(gemm_relu_kernel,
                             cudaFuncAttributeMaxDynamicSharedMemorySize,
                             GEMM_SMEM_BYTES);
    }

    // Fork: GEMM (V,W,b -> H) concurrent with CSR build (src,dst).
    cudaEventRecord(ev_fork, 0);
    cudaStreamWaitEvent(s_gemm, ev_fork, 0);
    gemm_relu_kernel<<<(N_NODES + 63) / 64, 256, GEMM_SMEM_BYTES, s_gemm>>>(V, W, b, H);
    cudaEventRecord(ev_gemm, s_gemm);

    prep_kernel<<<(N_PAD + 255) / 256, 256>>>((const unsigned int*)src);
    hist_kernel<<<(N_EDGES + 255) / 256, 256>>>(dst);
    scan1_kernel<<<N_PART, 1024>>>();
    scan2_kernel<<<1, 64>>>();
    scan3_kernel<<<N_PART, 1024>>>();
    fill_kernel<<<(N_EDGES + 255) / 256, 256>>>(src, dst);

    // Join: aggregate needs both H and the CSR.
    cudaStreamWaitEvent(0, ev_gemm, 0);
    aggregate_kernel<<<(N_NODES + 7) / 8, 256>>>(H, out);
}

// round 5
// speedup vs baseline: 3.4051x; 1.0924x over previous
#include <cuda_runtime.h>
#include <cuda_fp16.h>
#include <cstdint>

#define N_NODES 50000
#define N_EDGES 800000
#define DIM 128
#define N_PAD 53248               // 52 * 1024
#define N_PART 52

// ---------------------------------------------------------------------------
// Device scratch
// ---------------------------------------------------------------------------
__device__ __align__(16) __half g_H[N_NODES * DIM];  // relu(V@W^T+b), fp16
__device__ __align__(16) int g_deg[N_PAD];           // in-degree histogram
__device__ __align__(16) int g_offs[N_PAD + 4];      // CSR row offsets (by dst)
__device__ __align__(16) int g_cursor[N_PAD];        // fill cursors
__device__ int g_csr_src[N_EDGES];                   // CSR columns (src node)
__device__ int g_part[64];                           // block partial sums
__device__ int g_bsum[64];                           // exclusive block prefixes
__device__ int g_idx32;                              // 1 if indices are int32

// ---------------------------------------------------------------------------
// prep: zero degree array; block 0 detects index dtype
// ---------------------------------------------------------------------------
__global__ void prep_kernel(const unsigned int* __restrict__ srcw) {
    int i = blockIdx.x * blockDim.x + threadIdx.x;
    if (i < N_PAD) g_deg[i] = 0;
    if (blockIdx.x == 0) {
        __shared__ int found;
        if (threadIdx.x == 0) found = 0;
        __syncthreads();
        for (int j = threadIdx.x; j < 2048; j += blockDim.x)
            if (srcw[2 * j + 1] != 0u) found = 1;
        __syncthreads();
        if (threadIdx.x == 0) g_idx32 = found;
    }
}

__device__ __forceinline__ int load_idx(const void* p, int e) {
    return g_idx32 ? ((const int*)p)[e] : (int)((const long long*)p)[e];
}

__global__ __launch_bounds__(256) void hist_kernel(const void* __restrict__ dstp) {
    int e = blockIdx.x * blockDim.x + threadIdx.x;
    if (e >= N_EDGES) return;
    atomicAdd(&g_deg[load_idx(dstp, e)], 1);
}

// ---------------------------------------------------------------------------
// Parallel scan, 3 phases.
// ---------------------------------------------------------------------------
__global__ __launch_bounds__(1024) void scan1_kernel() {
    __shared__ int wsum[32];
    const int t = threadIdx.x, lane = t & 31, wid = t >> 5;
    int v = g_deg[blockIdx.x * 1024 + t];
    #pragma unroll
    for (int o = 16; o > 0; o >>= 1) v += __shfl_down_sync(~0u, v, o);
    if (lane == 0) wsum[wid] = v;
    __syncthreads();
    if (wid == 0) {
        int s = wsum[lane];
        #pragma unroll
        for (int o = 16; o > 0; o >>= 1) s += __shfl_down_sync(~0u, s, o);
        if (lane == 0) g_part[blockIdx.x] = s;
    }
}

__global__ void scan2_kernel() {
    __shared__ int sm[64];
    const int t = threadIdx.x;
    sm[t] = (t < N_PART) ? g_part[t] : 0;
    __syncthreads();
    #pragma unroll
    for (int off = 1; off < 64; off <<= 1) {
        int v = (t >= off) ? sm[t - off] : 0;
        __syncthreads();
        sm[t] += v;
        __syncthreads();
    }
    if (t < N_PART) g_bsum[t] = sm[t] - g_part[t];  // exclusive
}

__global__ __launch_bounds__(1024) void scan3_kernel() {
    __shared__ int wsum[33];
    const int t = threadIdx.x, lane = t & 31, wid = t >> 5;
    const int i = blockIdx.x * 1024 + t;
    int v = g_deg[i];
    int x = v;
    #pragma unroll
    for (int o = 1; o < 32; o <<= 1) {
        int y = __shfl_up_sync(~0u, x, o);
        if (lane >= o) x += y;
    }
    if (lane == 31) wsum[wid + 1] = x;
    __syncthreads();
    if (wid == 0) {
        int s = (lane < 31) ? wsum[lane + 1] : 0;
        #pragma unroll
        for (int o = 1; o < 32; o <<= 1) {
            int y = __shfl_up_sync(~0u, s, o);
            if (lane >= o) s += y;
        }
        wsum[lane + 1] = s;
        if (lane == 0) wsum[0] = 0;
    }
    __syncthreads();
    int excl = (x - v) + wsum[wid] + g_bsum[blockIdx.x];
    g_offs[i] = excl;
    g_cursor[i] = excl;
}

__global__ __launch_bounds__(256) void fill_kernel(const void* __restrict__ srcp,
                                                   const void* __restrict__ dstp) {
    int e = blockIdx.x * blockDim.x + threadIdx.x;
    if (e >= N_EDGES) return;
    int s = load_idx(srcp, e);
    int d = load_idx(dstp, e);
    int p = atomicAdd(&g_cursor[d], 1);
    g_csr_src[p] = s;
}

// ---------------------------------------------------------------------------
// GEMM + bias + ReLU (fp32 compute via fma.rn.f32x2, fp16 output).
// ---------------------------------------------------------------------------
#define GEMM_SMEM_BYTES ((64 * 132 + 128 * 128) * 4)

__device__ __forceinline__ void ffma2(unsigned long long& acc,
                                      unsigned long long a,
                                      unsigned long long b) {
    asm("fma.rn.f32x2 %0, %1, %2, %0;" : "+l"(acc) : "l"(a), "l"(b));
}

__global__ __launch_bounds__(256, 2) void gemm_relu_kernel(
    const float* __restrict__ V, const float* __restrict__ W,
    const float* __restrict__ b, __half* __restrict__ H) {
    extern __shared__ float smem[];
    float* Vs = smem;                 // [64][132]
    float* Ws = smem + 64 * 132;      // [128][128], float4-col swizzle by (d&31)

    const int tid = threadIdx.x;
    const int tx  = tid & 31;
    const int ty  = tid >> 5;
    const int n0  = blockIdx.x * 64;

    #pragma unroll
    for (int j = 0; j < 8; j++) {
        int f = tid + j * 256;
        int n = f >> 5;
        int c4 = (f & 31) << 2;
        int node = n0 + n;
        float4 v = (node < N_NODES) ? *(const float4*)(V + node * DIM + c4)
                                    : make_float4(0.f, 0.f, 0.f, 0.f);
        *(float4*)(Vs + n * 132 + c4) = v;
    }
    #pragma unroll
    for (int j = 0; j < 16; j++) {
        int p  = tid + j * 256;
        int d  = p >> 5;
        int c4 = p & 31;
        float4 w = *(const float4*)(W + d * DIM + (c4 << 2));
        *(float4*)(Ws + d * DIM + ((c4 ^ (d & 31)) << 2)) = w;
    }
    __syncthreads();

    unsigned long long acc[8][4];
    #pragma unroll
    for (int a = 0; a < 8; a++)
        #pragma unroll
        for (int c = 0; c < 4; c++) acc[a][c] = 0ull;

    #pragma unroll 2
    for (int k4 = 0; k4 < 32; k4++) {
        ulonglong2 wv[4];
        const int kw = ((k4 ^ tx) << 2);
        #pragma unroll
        for (int c = 0; c < 4; c++)
            wv[c] = *(const ulonglong2*)(Ws + (tx + 32 * c) * DIM + kw);
        ulonglong2 vv[8];
        #pragma unroll
        for (int a = 0; a < 8; a++)
            vv[a] = *(const ulonglong2*)(Vs + (ty * 8 + a) * 132 + (k4 << 2));
        #pragma unroll
        for (int a = 0; a < 8; a++)
            #pragma unroll
            for (int c = 0; c < 4; c++) {
                ffma2(acc[a][c], vv[a].x, wv[c].x);
                ffma2(acc[a][c], vv[a].y, wv[c].y);
            }
    }

    float bv[4];
    #pragma unroll
    for (int c = 0; c < 4; c++) bv[c] = b[tx + 32 * c];
    #pragma unroll
    for (int a = 0; a < 8; a++) {
        int node = n0 + ty * 8 + a;
        if (node < N_NODES) {
            #pragma unroll
            for (int c = 0; c < 4; c++) {
                float2 f = *reinterpret_cast<float2*>(&acc[a][c]);
                float r = fmaxf(f.x + f.y + bv[c], 0.f);
                H[node * DIM + tx + 32 * c] = __float2half_rn(r);
            }
        }
    }
}

// ---------------------------------------------------------------------------
// Aggregate: one warp per dst node. Half-warp per edge (16 lanes x 8 halves
// = full 256B fp16 row, coalesced). Packed __hmax2 (valid: H >= 0).
// 4-deep gather batching per half-warp; shfl-xor-16 combine; fp32 writeback.
// ---------------------------------------------------------------------------
__device__ __forceinline__ unsigned hmax_u(unsigned a, unsigned b) {
    __half2 r = __hmax2(*reinterpret_cast<__half2*>(&a),
                        *reinterpret_cast<__half2*>(&b));
    return *reinterpret_cast<unsigned*>(&r);
}
__device__ __forceinline__ void vmax4(uint4& m, const uint4& h) {
    m.x = hmax_u(m.x, h.x); m.y = hmax_u(m.y, h.y);
    m.z = hmax_u(m.z, h.z); m.w = hmax_u(m.w, h.w);
}

__global__ __launch_bounds__(256) void aggregate_kernel(
    const uint4* __restrict__ H2, float* __restrict__ out) {
    const int node = blockIdx.x * 8 + (threadIdx.x >> 5);
    if (node >= N_NODES) return;
    const int lane = threadIdx.x & 31;
    const int half = lane >> 4;      // which edge parity this lane covers
    const int sub  = lane & 15;      // 16B chunk within the 256B row

    const int beg = g_offs[node];
    const int end = g_offs[node + 1];

    uint4 m = make_uint4(0u, 0u, 0u, 0u);   // fp16 +0 bit pattern
    int j = beg + half;
    for (; j + 6 < end; j += 8) {           // 4 edges per half-warp per iter
        int s0 = g_csr_src[j];
        int s1 = g_csr_src[j + 2];
        int s2 = g_csr_src[j + 4];
        int s3 = g_csr_src[j + 6];
        uint4 h0 = H2[s0 * 16 + sub];
        uint4 h1 = H2[s1 * 16 + sub];
        uint4 h2 = H2[s2 * 16 + sub];
        uint4 h3 = H2[s3 * 16 + sub];
        vmax4(m, h0); vmax4(m, h1); vmax4(m, h2); vmax4(m, h3);
    }
    for (; j < end; j += 2) {
        uint4 h = H2[g_csr_src[j] * 16 + sub];
        vmax4(m, h);
    }
    // combine the two edge-parity halves (lane i <-> lane i^16)
    m.x = hmax_u(m.x, __shfl_xor_sync(~0u, m.x, 16));
    m.y = hmax_u(m.y, __shfl_xor_sync(~0u, m.y, 16));
    m.z = hmax_u(m.z, __shfl_xor_sync(~0u, m.z, 16));
    m.w = hmax_u(m.w, __shfl_xor_sync(~0u, m.w, 16));

    if (half == 0) {
        float2 fx = __half22float2(*reinterpret_cast<__half2*>(&m.x));
        float2 fy = __half22float2(*reinterpret_cast<__half2*>(&m.y));
        float2 fz = __half22float2(*reinterpret_cast<__half2*>(&m.z));
        float2 fw = __half22float2(*reinterpret_cast<__half2*>(&m.w));
        float4* op = (float4*)(out + node * DIM + sub * 8);
        op[0] = make_float4(fx.x, fx.y, fy.x, fy.y);
        op[1] = make_float4(fz.x, fz.y, fw.x, fw.y);
    }
}

// ---------------------------------------------------------------------------
extern "C" void kernel_launch(void* const* d_in, const int* in_sizes, int n_in,
                              void* d_out, int out_size) {
    const float* V   = (const float*)d_in[0];
    const float* W   = (const float*)d_in[1];
    const float* b   = (const float*)d_in[2];
    const void*  src = d_in[3];
    const void*  dst = d_in[4];
    float* out = (float*)d_out;

    __half* H;
    cudaGetSymbolAddress((void**)&H, g_H);

    static cudaStream_t s_gemm = nullptr;
    static cudaEvent_t ev_fork = nullptr, ev_gemm = nullptr;
    if (!s_gemm) {
        cudaStreamCreateWithFlags(&s_gemm, cudaStreamNonBlocking);
        cudaEventCreateWithFlags(&ev_fork, cudaEventDisableTiming);
        cudaEventCreateWithFlags(&ev_gemm, cudaEventDisableTiming);
        cudaFuncSetAttribute(gemm_relu_kernel,
                             cudaFuncAttributeMaxDynamicSharedMemorySize,
                             GEMM_SMEM_BYTES);
    }

    // Fork: GEMM (V,W,b -> H) concurrent with CSR build (src,dst).
    cudaEventRecord(ev_fork, 0);
    cudaStreamWaitEvent(s_gemm, ev_fork, 0);
    gemm_relu_kernel<<<(N_NODES + 63) / 64, 256, GEMM_SMEM_BYTES, s_gemm>>>(V, W, b, H);
    cudaEventRecord(ev_gemm, s_gemm);

    prep_kernel<<<(N_PAD + 255) / 256, 256>>>((const unsigned int*)src);
    hist_kernel<<<(N_EDGES + 255) / 256, 256>>>(dst);
    scan1_kernel<<<N_PART, 1024>>>();
    scan2_kernel<<<1, 64>>>();
    scan3_kernel<<<N_PART, 1024>>>();
    fill_kernel<<<(N_EDGES + 255) / 256, 256>>>(src, dst);

    // Join: aggregate needs both H and the CSR.
    cudaStreamWaitEvent(0, ev_gemm, 0);
    aggregate_kernel<<<(N_NODES + 7) / 8, 256>>>((const uint4*)H, out);
}

// round 6
// speedup vs baseline: 4.3429x; 1.2754x over previous
#include <cuda_runtime.h>
#include <cuda_fp16.h>
#include <cstdint>

#define N_NODES 50000
#define N_EDGES 800000
#define DIM 128
#define N_PAD 53248               // 52 * 1024
#define N_PART 52

// ---------------------------------------------------------------------------
// Device scratch
// ---------------------------------------------------------------------------
__device__ __align__(16) __half g_H[N_NODES * DIM];  // relu(V@W^T+b), fp16
__device__ __align__(16) int g_deg[N_PAD];
__device__ __align__(16) int g_offs[N_PAD + 4];
__device__ __align__(16) int g_cursor[N_PAD];
__device__ int g_csr_src[N_EDGES];
__device__ int g_part[64];
__device__ int g_bsum[64];
__device__ int g_idx32;

// ---------------------------------------------------------------------------
__global__ void prep_kernel(const unsigned int* __restrict__ srcw) {
    int i = blockIdx.x * blockDim.x + threadIdx.x;
    if (i < N_PAD) g_deg[i] = 0;
    if (blockIdx.x == 0) {
        __shared__ int found;
        if (threadIdx.x == 0) found = 0;
        __syncthreads();
        for (int j = threadIdx.x; j < 2048; j += blockDim.x)
            if (srcw[2 * j + 1] != 0u) found = 1;
        __syncthreads();
        if (threadIdx.x == 0) g_idx32 = found;
    }
}

__device__ __forceinline__ int load_idx(const void* p, int e) {
    return g_idx32 ? ((const int*)p)[e] : (int)((const long long*)p)[e];
}

__global__ __launch_bounds__(256) void hist_kernel(const void* __restrict__ dstp) {
    int e = blockIdx.x * blockDim.x + threadIdx.x;
    if (e >= N_EDGES) return;
    atomicAdd(&g_deg[load_idx(dstp, e)], 1);
}

// ---------------------------------------------------------------------------
// Parallel scan, 3 phases.
// ---------------------------------------------------------------------------
__global__ __launch_bounds__(1024) void scan1_kernel() {
    __shared__ int wsum[32];
    const int t = threadIdx.x, lane = t & 31, wid = t >> 5;
    int v = g_deg[blockIdx.x * 1024 + t];
    #pragma unroll
    for (int o = 16; o > 0; o >>= 1) v += __shfl_down_sync(~0u, v, o);
    if (lane == 0) wsum[wid] = v;
    __syncthreads();
    if (wid == 0) {
        int s = wsum[lane];
        #pragma unroll
        for (int o = 16; o > 0; o >>= 1) s += __shfl_down_sync(~0u, s, o);
        if (lane == 0) g_part[blockIdx.x] = s;
    }
}

__global__ void scan2_kernel() {
    __shared__ int sm[64];
    const int t = threadIdx.x;
    sm[t] = (t < N_PART) ? g_part[t] : 0;
    __syncthreads();
    #pragma unroll
    for (int off = 1; off < 64; off <<= 1) {
        int v = (t >= off) ? sm[t - off] : 0;
        __syncthreads();
        sm[t] += v;
        __syncthreads();
    }
    if (t < N_PART) g_bsum[t] = sm[t] - g_part[t];
}

__global__ __launch_bounds__(1024) void scan3_kernel() {
    __shared__ int wsum[33];
    const int t = threadIdx.x, lane = t & 31, wid = t >> 5;
    const int i = blockIdx.x * 1024 + t;
    int v = g_deg[i];
    int x = v;
    #pragma unroll
    for (int o = 1; o < 32; o <<= 1) {
        int y = __shfl_up_sync(~0u, x, o);
        if (lane >= o) x += y;
    }
    if (lane == 31) wsum[wid + 1] = x;
    __syncthreads();
    if (wid == 0) {
        int s = (lane < 31) ? wsum[lane + 1] : 0;
        #pragma unroll
        for (int o = 1; o < 32; o <<= 1) {
            int y = __shfl_up_sync(~0u, s, o);
            if (lane >= o) s += y;
        }
        wsum[lane + 1] = s;
        if (lane == 0) wsum[0] = 0;
    }
    __syncthreads();
    int excl = (x - v) + wsum[wid] + g_bsum[blockIdx.x];
    g_offs[i] = excl;
    g_cursor[i] = excl;
}

__global__ __launch_bounds__(256) void fill_kernel(const void* __restrict__ srcp,
                                                   const void* __restrict__ dstp) {
    int e = blockIdx.x * blockDim.x + threadIdx.x;
    if (e >= N_EDGES) return;
    int s = load_idx(srcp, e);
    int d = load_idx(dstp, e);
    int p = atomicAdd(&g_cursor[d], 1);
    g_csr_src[p] = s;
}

// ---------------------------------------------------------------------------
// Tensor-core GEMM + bias + ReLU.
//   H[m][n] = relu(sum_k V[m][k] * W[n][k] + b[n]),  fp16 in, fp32 acc.
// Block: 256 thr (8 warps), tile 128m x 128n, K=128 resident in smem.
// Warp w: m-block (w&3)*32, n-block (w>>2)*64 -> 2x8 m16n8 mma tiles.
// smem rows padded to 136 halves (272B): ldmatrix conflict-free
// (272/4 = 68 == 4 mod 32; 8 rows x 4-bank chunks cover all 32 banks).
// ---------------------------------------------------------------------------
#define GEMM_SMEM_BYTES (2 * 128 * 136 * 2)
#define SROW 136

__device__ __forceinline__ void ldsm_x4(uint32_t& r0, uint32_t& r1,
                                        uint32_t& r2, uint32_t& r3,
                                        uint32_t saddr) {
    asm volatile("ldmatrix.sync.aligned.m8n8.x4.shared.b16 {%0,%1,%2,%3}, [%4];"
                 : "=r"(r0), "=r"(r1), "=r"(r2), "=r"(r3) : "r"(saddr));
}

__device__ __forceinline__ void mma_f16(float* d, const uint32_t* a,
                                        const uint32_t* b) {
    asm volatile(
        "mma.sync.aligned.m16n8k16.row.col.f32.f16.f16.f32 "
        "{%0,%1,%2,%3}, {%4,%5,%6,%7}, {%8,%9}, {%0,%1,%2,%3};"
        : "+f"(d[0]), "+f"(d[1]), "+f"(d[2]), "+f"(d[3])
        : "r"(a[0]), "r"(a[1]), "r"(a[2]), "r"(a[3]), "r"(b[0]), "r"(b[1]));
}

__global__ __launch_bounds__(256, 2) void gemm_relu_tc_kernel(
    const float* __restrict__ V, const float* __restrict__ W,
    const float* __restrict__ b, __half* __restrict__ H) {
    extern __shared__ __half sh[];
    __half* Vh = sh;                  // [128][SROW]
    __half* Wh = sh + 128 * SROW;     // [128][SROW]

    const int tid  = threadIdx.x;
    const int lane = tid & 31;
    const int wid  = tid >> 5;
    const int mb   = blockIdx.x * 128;

    // ---- load + fp32->fp16 convert into smem ----
    {
        const int row  = tid >> 1;            // 0..127
        const int cof  = (tid & 1) * 64;      // half-row
        const int node = mb + row;
        __half* vdst = Vh + row * SROW + cof;
        const float* vsrc = V + (long long)node * DIM + cof;
        #pragma unroll
        for (int i = 0; i < 16; i++) {
            float4 f = (node < N_NODES) ? *(const float4*)(vsrc + i * 4)
                                        : make_float4(0.f, 0.f, 0.f, 0.f);
            __half2 h01 = __floats2half2_rn(f.x, f.y);
            __half2 h23 = __floats2half2_rn(f.z, f.w);
            *(uint2*)(vdst + i * 4) = make_uint2(
                *reinterpret_cast<uint32_t*>(&h01),
                *reinterpret_cast<uint32_t*>(&h23));
        }
        __half* wdst = Wh + row * SROW + cof;
        const float* wsrc = W + row * DIM + cof;
        #pragma unroll
        for (int i = 0; i < 16; i++) {
            float4 f = *(const float4*)(wsrc + i * 4);
            __half2 h01 = __floats2half2_rn(f.x, f.y);
            __half2 h23 = __floats2half2_rn(f.z, f.w);
            *(uint2*)(wdst + i * 4) = make_uint2(
                *reinterpret_cast<uint32_t*>(&h01),
                *reinterpret_cast<uint32_t*>(&h23));
        }
    }
    __syncthreads();

    const int mw = (wid & 3) * 32;    // warp m offset within tile
    const int nw = (wid >> 2) * 64;   // warp n offset within tile
    const int g  = lane >> 3;         // ldmatrix address group

    const uint32_t vbase = (uint32_t)__cvta_generic_to_shared(Vh);
    const uint32_t wbase = (uint32_t)__cvta_generic_to_shared(Wh);

    // per-thread ldmatrix row/col offsets (halves)
    const int a_row = mw + (lane & 7) + ((g & 1) << 3);
    const int a_col = (g >> 1) << 3;
    const int b_row = nw + (lane & 7) + ((g >> 1) << 3);
    const int b_col = (g & 1) << 3;

    float acc[2][8][4];
    #pragma unroll
    for (int mt = 0; mt < 2; mt++)
        #pragma unroll
        for (int nt = 0; nt < 8; nt++)
            #pragma unroll
            for (int r = 0; r < 4; r++) acc[mt][nt][r] = 0.f;

    #pragma unroll
    for (int ks = 0; ks < 8; ks++) {
        const int k0 = ks * 16;
        uint32_t a[2][4];
        #pragma unroll
        for (int mt = 0; mt < 2; mt++)
            ldsm_x4(a[mt][0], a[mt][1], a[mt][2], a[mt][3],
                    vbase + ((a_row + mt * 16) * SROW + k0 + a_col) * 2);
        uint32_t bf[8][2];
        #pragma unroll
        for (int np = 0; np < 4; np++) {
            uint32_t r0, r1, r2, r3;
            ldsm_x4(r0, r1, r2, r3,
                    wbase + ((b_row + np * 16) * SROW + k0 + b_col) * 2);
            bf[np * 2][0] = r0;  bf[np * 2][1] = r1;
            bf[np * 2 + 1][0] = r2;  bf[np * 2 + 1][1] = r3;
        }
        #pragma unroll
        for (int mt = 0; mt < 2; mt++)
            #pragma unroll
            for (int nt = 0; nt < 8; nt++)
                mma_f16(acc[mt][nt], a[mt], bf[nt]);
    }

    // ---- epilogue: bias + relu + fp16 store ----
    const int qr = lane >> 2;          // row within m16 tile
    const int qc = (lane & 3) << 1;    // col pair within n8 tile
    #pragma unroll
    for (int nt = 0; nt < 8; nt++) {
        const int n = nw + nt * 8 + qc;
        const float2 bb = *(const float2*)(b + n);
        #pragma unroll
        for (int mt = 0; mt < 2; mt++) {
            const int m0 = mb + mw + mt * 16 + qr;
            const float* c = acc[mt][nt];
            if (m0 < N_NODES) {
                __half2 h = __floats2half2_rn(fmaxf(c[0] + bb.x, 0.f),
                                              fmaxf(c[1] + bb.y, 0.f));
                *(__half2*)(H + m0 * DIM + n) = h;
            }
            if (m0 + 8 < N_NODES) {
                __half2 h = __floats2half2_rn(fmaxf(c[2] + bb.x, 0.f),
                                              fmaxf(c[3] + bb.y, 0.f));
                *(__half2*)(H + (m0 + 8) * DIM + n) = h;
            }
        }
    }
}

// ---------------------------------------------------------------------------
// Aggregate: one warp per dst node, half-warp per edge, packed __hmax2.
// ---------------------------------------------------------------------------
__device__ __forceinline__ unsigned hmax_u(unsigned a, unsigned b) {
    __half2 r = __hmax2(*reinterpret_cast<__half2*>(&a),
                        *reinterpret_cast<__half2*>(&b));
    return *reinterpret_cast<unsigned*>(&r);
}
__device__ __forceinline__ void vmax4(uint4& m, const uint4& h) {
    m.x = hmax_u(m.x, h.x); m.y = hmax_u(m.y, h.y);
    m.z = hmax_u(m.z, h.z); m.w = hmax_u(m.w, h.w);
}

__global__ __launch_bounds__(256) void aggregate_kernel(
    const uint4* __restrict__ H2, float* __restrict__ out) {
    const int node = blockIdx.x * 8 + (threadIdx.x >> 5);
    if (node >= N_NODES) return;
    const int lane = threadIdx.x & 31;
    const int half = lane >> 4;
    const int sub  = lane & 15;

    const int beg = g_offs[node];
    const int end = g_offs[node + 1];

    uint4 m = make_uint4(0u, 0u, 0u, 0u);
    int j = beg + half;
    for (; j + 6 < end; j += 8) {
        int s0 = g_csr_src[j];
        int s1 = g_csr_src[j + 2];
        int s2 = g_csr_src[j + 4];
        int s3 = g_csr_src[j + 6];
        uint4 h0 = H2[s0 * 16 + sub];
        uint4 h1 = H2[s1 * 16 + sub];
        uint4 h2 = H2[s2 * 16 + sub];
        uint4 h3 = H2[s3 * 16 + sub];
        vmax4(m, h0); vmax4(m, h1); vmax4(m, h2); vmax4(m, h3);
    }
    for (; j < end; j += 2) {
        uint4 h = H2[g_csr_src[j] * 16 + sub];
        vmax4(m, h);
    }
    m.x = hmax_u(m.x, __shfl_xor_sync(~0u, m.x, 16));
    m.y = hmax_u(m.y, __shfl_xor_sync(~0u, m.y, 16));
    m.z = hmax_u(m.z, __shfl_xor_sync(~0u, m.z, 16));
    m.w = hmax_u(m.w, __shfl_xor_sync(~0u, m.w, 16));

    if (half == 0) {
        float2 fx = __half22float2(*reinterpret_cast<__half2*>(&m.x));
        float2 fy = __half22float2(*reinterpret_cast<__half2*>(&m.y));
        float2 fz = __half22float2(*reinterpret_cast<__half2*>(&m.z));
        float2 fw = __half22float2(*reinterpret_cast<__half2*>(&m.w));
        float4* op = (float4*)(out + node * DIM + sub * 8);
        op[0] = make_float4(fx.x, fx.y, fy.x, fy.y);
        op[1] = make_float4(fz.x, fz.y, fw.x, fw.y);
    }
}

// ---------------------------------------------------------------------------
extern "C" void kernel_launch(void* const* d_in, const int* in_sizes, int n_in,
                              void* d_out, int out_size) {
    const float* V   = (const float*)d_in[0];
    const float* W   = (const float*)d_in[1];
    const float* b   = (const float*)d_in[2];
    const void*  src = d_in[3];
    const void*  dst = d_in[4];
    float* out = (float*)d_out;

    __half* H;
    cudaGetSymbolAddress((void**)&H, g_H);

    static cudaStream_t s_gemm = nullptr;
    static cudaEvent_t ev_fork = nullptr, ev_gemm = nullptr;
    if (!s_gemm) {
        cudaStreamCreateWithFlags(&s_gemm, cudaStreamNonBlocking);
        cudaEventCreateWithFlags(&ev_fork, cudaEventDisableTiming);
        cudaEventCreateWithFlags(&ev_gemm, cudaEventDisableTiming);
        cudaFuncSetAttribute(gemm_relu_tc_kernel,
                             cudaFuncAttributeMaxDynamicSharedMemorySize,
                             GEMM_SMEM_BYTES);
    }

    // Fork: GEMM (V,W,b -> H) concurrent with CSR build (src,dst).
    cudaEventRecord(ev_fork, 0);
    cudaStreamWaitEvent(s_gemm, ev_fork, 0);
    gemm_relu_tc_kernel<<<(N_NODES + 127) / 128, 256, GEMM_SMEM_BYTES, s_gemm>>>(
        V, W, b, H);
    cudaEventRecord(ev_gemm, s_gemm);

    prep_kernel<<<(N_PAD + 255) / 256, 256>>>((const unsigned int*)src);
    hist_kernel<<<(N_EDGES + 255) / 256, 256>>>(dst);
    scan1_kernel<<<N_PART, 1024>>>();
    scan2_kernel<<<1, 64>>>();
    scan3_kernel<<<N_PART, 1024>>>();
    fill_kernel<<<(N_EDGES + 255) / 256, 256>>>(src, dst);

    // Join: aggregate needs both H and the CSR.
    cudaStreamWaitEvent(0, ev_gemm, 0);
    aggregate_kernel<<<(N_NODES + 7) / 8, 256>>>((const uint4*)H, out);
}

// round 7
// speedup vs baseline: 5.0609x; 1.1653x over previous
#include <cuda_runtime.h>
#include <cuda_fp16.h>
#include <cstdint>

#define N_NODES 50000
#define N_EDGES 800000
#define DIM 128
#define BCAP 64                   // bucket capacity (P(deg>64) ~ 1e-18)

// ---------------------------------------------------------------------------
// Device scratch
// ---------------------------------------------------------------------------
__device__ __align__(16) __half g_H[N_NODES * DIM];   // relu(V@W^T+b), fp16
__device__ __align__(16) int g_deg[N_NODES];          // in-degree (cursor)
__device__ __align__(16) int g_bucket[N_NODES * BCAP];// src indices per dst
__device__ int g_idx32;                               // 1 if indices are int32

// ---------------------------------------------------------------------------
// prep: zero degree array; block 0 detects index dtype
// (int64 indices < 50000 have all-zero high 32-bit words).
// ---------------------------------------------------------------------------
__global__ void prep_kernel(const unsigned int* __restrict__ srcw) {
    int i = blockIdx.x * blockDim.x + threadIdx.x;
    if (i < N_NODES) g_deg[i] = 0;
    if (blockIdx.x == 0) {
        __shared__ int found;
        if (threadIdx.x == 0) found = 0;
        __syncthreads();
        for (int j = threadIdx.x; j < 2048; j += blockDim.x)
            if (srcw[2 * j + 1] != 0u) found = 1;
        __syncthreads();
        if (threadIdx.x == 0) g_idx32 = found;
    }
}

__device__ __forceinline__ int load_idx(const void* p, int e) {
    return g_idx32 ? ((const int*)p)[e] : (int)((const long long*)p)[e];
}

// ---------------------------------------------------------------------------
// Fused hist+fill: one atomic per edge, one pass over the edge list.
// ---------------------------------------------------------------------------
__global__ __launch_bounds__(256) void bucket_fill_kernel(
    const void* __restrict__ srcp, const void* __restrict__ dstp) {
    int e = blockIdx.x * blockDim.x + threadIdx.x;
    if (e >= N_EDGES) return;
    int s = load_idx(srcp, e);
    int d = load_idx(dstp, e);
    int pos = atomicAdd(&g_deg[d], 1);
    if (pos < BCAP) g_bucket[(d << 6) + pos] = s;
}

// ---------------------------------------------------------------------------
// Tensor-core GEMM + bias + ReLU (fp16 in via smem convert, fp32 acc).
// Block: 256 thr (8 warps), tile 128m x 128n, K=128 resident in smem.
// smem rows padded to 136 halves -> ldmatrix conflict-free.
// ---------------------------------------------------------------------------
#define GEMM_SMEM_BYTES (2 * 128 * 136 * 2)
#define SROW 136

__device__ __forceinline__ void ldsm_x4(uint32_t& r0, uint32_t& r1,
                                        uint32_t& r2, uint32_t& r3,
                                        uint32_t saddr) {
    asm volatile("ldmatrix.sync.aligned.m8n8.x4.shared.b16 {%0,%1,%2,%3}, [%4];"
                 : "=r"(r0), "=r"(r1), "=r"(r2), "=r"(r3) : "r"(saddr));
}

__device__ __forceinline__ void mma_f16(float* d, const uint32_t* a,
                                        const uint32_t* b) {
    asm volatile(
        "mma.sync.aligned.m16n8k16.row.col.f32.f16.f16.f32 "
        "{%0,%1,%2,%3}, {%4,%5,%6,%7}, {%8,%9}, {%0,%1,%2,%3};"
        : "+f"(d[0]), "+f"(d[1]), "+f"(d[2]), "+f"(d[3])
        : "r"(a[0]), "r"(a[1]), "r"(a[2]), "r"(a[3]), "r"(b[0]), "r"(b[1]));
}

__global__ __launch_bounds__(256, 2) void gemm_relu_tc_kernel(
    const float* __restrict__ V, const float* __restrict__ W,
    const float* __restrict__ b, __half* __restrict__ H) {
    extern __shared__ __half sh[];
    __half* Vh = sh;                  // [128][SROW]
    __half* Wh = sh + 128 * SROW;     // [128][SROW]

    const int tid  = threadIdx.x;
    const int lane = tid & 31;
    const int wid  = tid >> 5;
    const int mb   = blockIdx.x * 128;

    // ---- load + fp32->fp16 convert into smem ----
    {
        const int row  = tid >> 1;
        const int cof  = (tid & 1) * 64;
        const int node = mb + row;
        __half* vdst = Vh + row * SROW + cof;
        const float* vsrc = V + (long long)node * DIM + cof;
        #pragma unroll
        for (int i = 0; i < 16; i++) {
            float4 f = (node < N_NODES) ? *(const float4*)(vsrc + i * 4)
                                        : make_float4(0.f, 0.f, 0.f, 0.f);
            __half2 h01 = __floats2half2_rn(f.x, f.y);
            __half2 h23 = __floats2half2_rn(f.z, f.w);
            *(uint2*)(vdst + i * 4) = make_uint2(
                *reinterpret_cast<uint32_t*>(&h01),
                *reinterpret_cast<uint32_t*>(&h23));
        }
        __half* wdst = Wh + row * SROW + cof;
        const float* wsrc = W + row * DIM + cof;
        #pragma unroll
        for (int i = 0; i < 16; i++) {
            float4 f = *(const float4*)(wsrc + i * 4);
            __half2 h01 = __floats2half2_rn(f.x, f.y);
            __half2 h23 = __floats2half2_rn(f.z, f.w);
            *(uint2*)(wdst + i * 4) = make_uint2(
                *reinterpret_cast<uint32_t*>(&h01),
                *reinterpret_cast<uint32_t*>(&h23));
        }
    }
    __syncthreads();

    const int mw = (wid & 3) * 32;
    const int nw = (wid >> 2) * 64;
    const int g  = lane >> 3;

    const uint32_t vbase = (uint32_t)__cvta_generic_to_shared(Vh);
    const uint32_t wbase = (uint32_t)__cvta_generic_to_shared(Wh);

    const int a_row = mw + (lane & 7) + ((g & 1) << 3);
    const int a_col = (g >> 1) << 3;
    const int b_row = nw + (lane & 7) + ((g >> 1) << 3);
    const int b_col = (g & 1) << 3;

    float acc[2][8][4];
    #pragma unroll
    for (int mt = 0; mt < 2; mt++)
        #pragma unroll
        for (int nt = 0; nt < 8; nt++)
            #pragma unroll
            for (int r = 0; r < 4; r++) acc[mt][nt][r] = 0.f;

    #pragma unroll
    for (int ks = 0; ks < 8; ks++) {
        const int k0 = ks * 16;
        uint32_t a[2][4];
        #pragma unroll
        for (int mt = 0; mt < 2; mt++)
            ldsm_x4(a[mt][0], a[mt][1], a[mt][2], a[mt][3],
                    vbase + ((a_row + mt * 16) * SROW + k0 + a_col) * 2);
        uint32_t bf[8][2];
        #pragma unroll
        for (int np = 0; np < 4; np++) {
            uint32_t r0, r1, r2, r3;
            ldsm_x4(r0, r1, r2, r3,
                    wbase + ((b_row + np * 16) * SROW + k0 + b_col) * 2);
            bf[np * 2][0] = r0;  bf[np * 2][1] = r1;
            bf[np * 2 + 1][0] = r2;  bf[np * 2 + 1][1] = r3;
        }
        #pragma unroll
        for (int mt = 0; mt < 2; mt++)
            #pragma unroll
            for (int nt = 0; nt < 8; nt++)
                mma_f16(acc[mt][nt], a[mt], bf[nt]);
    }

    // ---- epilogue: bias + relu + fp16 store ----
    const int qr = lane >> 2;
    const int qc = (lane & 3) << 1;
    #pragma unroll
    for (int nt = 0; nt < 8; nt++) {
        const int n = nw + nt * 8 + qc;
        const float2 bb = *(const float2*)(b + n);
        #pragma unroll
        for (int mt = 0; mt < 2; mt++) {
            const int m0 = mb + mw + mt * 16 + qr;
            const float* c = acc[mt][nt];
            if (m0 < N_NODES) {
                __half2 h = __floats2half2_rn(fmaxf(c[0] + bb.x, 0.f),
                                              fmaxf(c[1] + bb.y, 0.f));
                *(__half2*)(H + m0 * DIM + n) = h;
            }
            if (m0 + 8 < N_NODES) {
                __half2 h = __floats2half2_rn(fmaxf(c[2] + bb.x, 0.f),
                                              fmaxf(c[3] + bb.y, 0.f));
                *(__half2*)(H + (m0 + 8) * DIM + n) = h;
            }
        }
    }
}

// ---------------------------------------------------------------------------
// Aggregate: one warp per dst node, half-warp per edge, packed __hmax2.
// Edge sources come from the node's contiguous bucket row.
// ---------------------------------------------------------------------------
__device__ __forceinline__ unsigned hmax_u(unsigned a, unsigned b) {
    __half2 r = __hmax2(*reinterpret_cast<__half2*>(&a),
                        *reinterpret_cast<__half2*>(&b));
    return *reinterpret_cast<unsigned*>(&r);
}
__device__ __forceinline__ void vmax4(uint4& m, const uint4& h) {
    m.x = hmax_u(m.x, h.x); m.y = hmax_u(m.y, h.y);
    m.z = hmax_u(m.z, h.z); m.w = hmax_u(m.w, h.w);
}

__global__ __launch_bounds__(256) void aggregate_kernel(
    const uint4* __restrict__ H2, float* __restrict__ out) {
    const int node = blockIdx.x * 8 + (threadIdx.x >> 5);
    if (node >= N_NODES) return;
    const int lane = threadIdx.x & 31;
    const int half = lane >> 4;
    const int sub  = lane & 15;

    const int deg = min(g_deg[node], BCAP);
    const int* __restrict__ bucket = g_bucket + (node << 6);

    uint4 m = make_uint4(0u, 0u, 0u, 0u);
    int j = half;
    for (; j + 6 < deg; j += 8) {
        int s0 = bucket[j];
        int s1 = bucket[j + 2];
        int s2 = bucket[j + 4];
        int s3 = bucket[j + 6];
        uint4 h0 = H2[s0 * 16 + sub];
        uint4 h1 = H2[s1 * 16 + sub];
        uint4 h2 = H2[s2 * 16 + sub];
        uint4 h3 = H2[s3 * 16 + sub];
        vmax4(m, h0); vmax4(m, h1); vmax4(m, h2); vmax4(m, h3);
    }
    for (; j < deg; j += 2) {
        uint4 h = H2[bucket[j] * 16 + sub];
        vmax4(m, h);
    }
    m.x = hmax_u(m.x, __shfl_xor_sync(~0u, m.x, 16));
    m.y = hmax_u(m.y, __shfl_xor_sync(~0u, m.y, 16));
    m.z = hmax_u(m.z, __shfl_xor_sync(~0u, m.z, 16));
    m.w = hmax_u(m.w, __shfl_xor_sync(~0u, m.w, 16));

    if (half == 0) {
        float2 fx = __half22float2(*reinterpret_cast<__half2*>(&m.x));
        float2 fy = __half22float2(*reinterpret_cast<__half2*>(&m.y));
        float2 fz = __half22float2(*reinterpret_cast<__half2*>(&m.z));
        float2 fw = __half22float2(*reinterpret_cast<__half2*>(&m.w));
        float4* op = (float4*)(out + node * DIM + sub * 8);
        op[0] = make_float4(fx.x, fx.y, fy.x, fy.y);
        op[1] = make_float4(fz.x, fz.y, fw.x, fw.y);
    }
}

// ---------------------------------------------------------------------------
extern "C" void kernel_launch(void* const* d_in, const int* in_sizes, int n_in,
                              void* d_out, int out_size) {
    const float* V   = (const float*)d_in[0];
    const float* W   = (const float*)d_in[1];
    const float* b   = (const float*)d_in[2];
    const void*  src = d_in[3];
    const void*  dst = d_in[4];
    float* out = (float*)d_out;

    __half* H;
    cudaGetSymbolAddress((void**)&H, g_H);

    static cudaStream_t s_gemm = nullptr;
    static cudaEvent_t ev_fork = nullptr, ev_gemm = nullptr;
    if (!s_gemm) {
        cudaStreamCreateWithFlags(&s_gemm, cudaStreamNonBlocking);
        cudaEventCreateWithFlags(&ev_fork, cudaEventDisableTiming);
        cudaEventCreateWithFlags(&ev_gemm, cudaEventDisableTiming);
        cudaFuncSetAttribute(gemm_relu_tc_kernel,
                             cudaFuncAttributeMaxDynamicSharedMemorySize,
                             GEMM_SMEM_BYTES);
    }

    // Fork: GEMM (V,W,b -> H) concurrent with bucket build (src,dst).
    cudaEventRecord(ev_fork, 0);
    cudaStreamWaitEvent(s_gemm, ev_fork, 0);
    gemm_relu_tc_kernel<<<(N_NODES + 127) / 128, 256, GEMM_SMEM_BYTES, s_gemm>>>(
        V, W, b, H);
    cudaEventRecord(ev_gemm, s_gemm);

    prep_kernel<<<(N_NODES + 255) / 256, 256>>>((const unsigned int*)src);
    bucket_fill_kernel<<<(N_EDGES + 255) / 256, 256>>>(src, dst);

    // Join: aggregate needs both H and the buckets.
    cudaStreamWaitEvent(0, ev_gemm, 0);
    aggregate_kernel<<<(N_NODES + 7) / 8, 256>>>((const uint4*)H, out);
}